// round 10
// baseline (speedup 1.0000x reference)
#include <cuda_runtime.h>
#include <cuda_bf16.h>
#include <math.h>
#include <stdint.h>

#define N_NODES   100000
#define N_EDGES   1600000
#define IN_DIM    256
#define HID       64
#define CLS       32
#define NEG_SLOPE 0.01f
#define NBLK_SCAN ((N_NODES + 255) / 256)   // 391

#define BM      128
#define KCHUNK  128
#define KPAD    136
#define GEMM1_SMEM (2 * BM * KPAD * 2)      // 69632 B

// ---------------- scratch (device globals; no allocations allowed) ----------
__device__ float    g_Hw1[N_NODES * HID];
__device__ float    g_Hw2[N_NODES * CLS];
__device__ float    g_s[N_NODES];            // layer-1 scores
__device__ float    g_d[N_NODES];
__device__ float    g_s2[N_NODES];           // layer-2 scores
__device__ float    g_d2[N_NODES];
__device__ int      g_deg[N_NODES];
__device__ int      g_off[N_NODES];          // within-block exclusive scan
__device__ int      g_pos[N_NODES];
__device__ int      g_csr_dst[N_EDGES];
__device__ int      g_bsum[NBLK_SCAN];
__device__ int      g_bscan[NBLK_SCAN];
__device__ uint32_t g_Wpack[2 * 16 * 8 * 32 * 2];

__device__ __forceinline__ int seg_beg(int n) {
    return g_off[n] + g_bscan[n >> 8];
}
__device__ __forceinline__ int seg_end(int n) {
    return (n + 1 < N_NODES) ? (g_off[n + 1] + g_bscan[(n + 1) >> 8]) : N_EDGES;
}

// ================= CSR chain (side stream) ==================================
__global__ void k_zero() {
    int i = blockIdx.x * blockDim.x + threadIdx.x;
    if (i < N_NODES) { g_deg[i] = 0; g_pos[i] = 0; }
}

__global__ void k_count(const int* __restrict__ ei) {
    int i = blockIdx.x * blockDim.x + threadIdx.x;
    if (i < N_EDGES) atomicAdd(&g_deg[ei[i]], 1);
}

__global__ void k_scan1() {
    __shared__ int sh[256];
    int t = threadIdx.x;
    int i = blockIdx.x * 256 + t;
    int v = (i < N_NODES) ? g_deg[i] : 0;
    sh[t] = v;
    __syncthreads();
#pragma unroll
    for (int o = 1; o < 256; o <<= 1) {
        int x = (t >= o) ? sh[t - o] : 0;
        __syncthreads();
        sh[t] += x;
        __syncthreads();
    }
    if (i < N_NODES) g_off[i] = sh[t] - v;
    if (t == 255) g_bsum[blockIdx.x] = sh[255];
}

__global__ void k_scan2() {
    __shared__ int sh[512];
    int t = threadIdx.x;
    int v = (t < NBLK_SCAN) ? g_bsum[t] : 0;
    sh[t] = v;
    __syncthreads();
#pragma unroll
    for (int o = 1; o < 512; o <<= 1) {
        int x = (t >= o) ? sh[t - o] : 0;
        __syncthreads();
        sh[t] += x;
        __syncthreads();
    }
    if (t < NBLK_SCAN) g_bscan[t] = sh[t] - v;
}

__global__ void k_fill(const int* __restrict__ ei) {
    int i = blockIdx.x * blockDim.x + threadIdx.x;
    if (i >= N_EDGES) return;
    int s = ei[i];
    int slot = seg_beg(s) + atomicAdd(&g_pos[s], 1);
    g_csr_dst[slot] = ei[N_EDGES + i];
}

// ================= W1 pack (main stream) =====================================
__global__ void k_packW(const float* __restrict__ W1) {
    int idx = blockIdx.x * blockDim.x + threadIdx.x;   // 0..4095
    int ks   = idx >> 8;
    int nb   = (idx >> 5) & 7;
    int lane = idx & 31;
    int n  = nb * 8 + (lane >> 2);
    int k0 = ks * 16 + (lane & 3) * 2;
#pragma unroll
    for (int r = 0; r < 2; ++r) {
        int k = k0 + r * 8;
        float w0 = W1[k * HID + n];
        float w1 = W1[(k + 1) * HID + n];
        __nv_bfloat162 h = __float22bfloat162_rn(make_float2(w0, w1));
        __nv_bfloat162 l = __float22bfloat162_rn(
            make_float2(w0 - __low2float(h), w1 - __high2float(h)));
        g_Wpack[((0 * 16 + ks) * 8 + nb) * 64 + lane * 2 + r] = *(uint32_t*)&h;
        g_Wpack[((1 * 16 + ks) * 8 + nb) * 64 + lane * 2 + r] = *(uint32_t*)&l;
    }
}

// ================= layer-1 GEMM (tensor cores, bf16 split) + scores ==========
__device__ __forceinline__ void mma16816(float* c, uint32_t a0, uint32_t a1,
                                         uint32_t a2, uint32_t a3,
                                         uint32_t b0, uint32_t b1) {
    asm volatile(
        "mma.sync.aligned.m16n8k16.row.col.f32.bf16.bf16.f32 "
        "{%0,%1,%2,%3}, {%4,%5,%6,%7}, {%8,%9}, {%0,%1,%2,%3};\n"
        : "+f"(c[0]), "+f"(c[1]), "+f"(c[2]), "+f"(c[3])
        : "r"(a0), "r"(a1), "r"(a2), "r"(a3), "r"(b0), "r"(b1));
}

__global__ __launch_bounds__(256) void k_gemm1_mma(const float* __restrict__ X,
                                                   const float* __restrict__ A1) {
    extern __shared__ unsigned short sm[];
    unsigned short* Ahi = sm;
    unsigned short* Alo = sm + BM * KPAD;

    int tid  = threadIdx.x;
    int warp = tid >> 5;
    int lane = tid & 31;
    int row0 = blockIdx.x * BM;

    float acc[8][4];
#pragma unroll
    for (int nb = 0; nb < 8; ++nb)
#pragma unroll
        for (int r = 0; r < 4; ++r) acc[nb][r] = 0.f;

    for (int chunk = 0; chunk < IN_DIM / KCHUNK; ++chunk) {
        __syncthreads();
        for (int i = tid; i < BM * (KCHUNK / 4); i += 256) {
            int r  = i >> 5;
            int c4 = i & 31;
            float4 v = make_float4(0.f, 0.f, 0.f, 0.f);
            if (row0 + r < N_NODES)
                v = __ldg((const float4*)(X + (size_t)(row0 + r) * IN_DIM
                                            + chunk * KCHUNK + c4 * 4));
            __nv_bfloat162 h01 = __float22bfloat162_rn(make_float2(v.x, v.y));
            __nv_bfloat162 h23 = __float22bfloat162_rn(make_float2(v.z, v.w));
            __nv_bfloat162 l01 = __float22bfloat162_rn(
                make_float2(v.x - __low2float(h01), v.y - __high2float(h01)));
            __nv_bfloat162 l23 = __float22bfloat162_rn(
                make_float2(v.z - __low2float(h23), v.w - __high2float(h23)));
            uint32_t base = r * KPAD + c4 * 4;
            *(uint32_t*)(Ahi + base)     = *(uint32_t*)&h01;
            *(uint32_t*)(Ahi + base + 2) = *(uint32_t*)&h23;
            *(uint32_t*)(Alo + base)     = *(uint32_t*)&l01;
            *(uint32_t*)(Alo + base + 2) = *(uint32_t*)&l23;
        }
        __syncthreads();

        int rA = warp * 16 + (lane >> 2);
#pragma unroll
        for (int ks = 0; ks < KCHUNK / 16; ++ks) {
            int kc = ks * 16 + (lane & 3) * 2;
            uint32_t ah0 = *(uint32_t*)(Ahi + rA * KPAD + kc);
            uint32_t ah1 = *(uint32_t*)(Ahi + (rA + 8) * KPAD + kc);
            uint32_t ah2 = *(uint32_t*)(Ahi + rA * KPAD + kc + 8);
            uint32_t ah3 = *(uint32_t*)(Ahi + (rA + 8) * KPAD + kc + 8);
            uint32_t al0 = *(uint32_t*)(Alo + rA * KPAD + kc);
            uint32_t al1 = *(uint32_t*)(Alo + (rA + 8) * KPAD + kc);
            uint32_t al2 = *(uint32_t*)(Alo + rA * KPAD + kc + 8);
            uint32_t al3 = *(uint32_t*)(Alo + (rA + 8) * KPAD + kc + 8);
            int ksg = chunk * (KCHUNK / 16) + ks;
#pragma unroll
            for (int nb = 0; nb < 8; ++nb) {
                uint2 bh = __ldg((const uint2*)(g_Wpack + ((0 * 16 + ksg) * 8 + nb) * 64 + lane * 2));
                uint2 bl = __ldg((const uint2*)(g_Wpack + ((1 * 16 + ksg) * 8 + nb) * 64 + lane * 2));
                mma16816(acc[nb], ah0, ah1, ah2, ah3, bh.x, bh.y);
                mma16816(acc[nb], ah0, ah1, ah2, ah3, bl.x, bl.y);
                mma16816(acc[nb], al0, al1, al2, al3, bh.x, bh.y);
            }
        }
    }

    int rowA = row0 + warp * 16 + (lane >> 2);
    int colA = (lane & 3) * 2;
#pragma unroll
    for (int nb = 0; nb < 8; ++nb) {
        int col = nb * 8 + colA;
        if (rowA < N_NODES)
            *(float2*)(g_Hw1 + (size_t)rowA * HID + col) = make_float2(acc[nb][0], acc[nb][1]);
        if (rowA + 8 < N_NODES)
            *(float2*)(g_Hw1 + (size_t)(rowA + 8) * HID + col) = make_float2(acc[nb][2], acc[nb][3]);
    }

    float s0 = 0.f, d0 = 0.f, s1 = 0.f, d1 = 0.f;
#pragma unroll
    for (int nb = 0; nb < 8; ++nb) {
        int col = nb * 8 + colA;
        float a0 = __ldg(&A1[col]),       a1 = __ldg(&A1[col + 1]);
        float b0 = __ldg(&A1[HID + col]), b1 = __ldg(&A1[HID + col + 1]);
        s0 += acc[nb][0] * a0 + acc[nb][1] * a1;
        d0 += acc[nb][0] * b0 + acc[nb][1] * b1;
        s1 += acc[nb][2] * a0 + acc[nb][3] * a1;
        d1 += acc[nb][2] * b0 + acc[nb][3] * b1;
    }
#pragma unroll
    for (int o = 1; o <= 2; o <<= 1) {
        s0 += __shfl_xor_sync(0xffffffffu, s0, o);
        d0 += __shfl_xor_sync(0xffffffffu, d0, o);
        s1 += __shfl_xor_sync(0xffffffffu, s1, o);
        d1 += __shfl_xor_sync(0xffffffffu, d1, o);
    }
    if ((lane & 3) == 0) {
        if (rowA < N_NODES)     { g_s[rowA] = s0;     g_d[rowA] = d0; }
        if (rowA + 8 < N_NODES) { g_s[rowA + 8] = s1; g_d[rowA + 8] = d1; }
    }
}

// ================= layer-1 softagg + ELU + fused gemm2 + scores ==============
// 512 threads = 16 nodes/block (halves per-block W2 smem reload traffic).
__global__ __launch_bounds__(512) void k_softagg64g2(const float* __restrict__ W2,
                                                     const float* __restrict__ A2) {
    __shared__ float W2s[HID * CLS];     // 8 KB
    __shared__ float A2s[2 * CLS];
    for (int i = threadIdx.x; i < HID * CLS; i += 512) W2s[i] = W2[i];
    if (threadIdx.x < 2 * CLS) A2s[threadIdx.x] = A2[threadIdx.x];
    __syncthreads();

    int n = blockIdx.x * 16 + (threadIdx.x >> 5);
    int lane = threadIdx.x & 31;
    int beg = seg_beg(n), end = seg_end(n);
    int deg = end - beg;
    float sn = g_s[n];

    int dk = 0; float ek = -1e30f;
    if (lane < deg) {
        dk = g_csr_dst[beg + lane];
        float e = sn + g_d[dk];
        ek = e > 0.f ? e : NEG_SLOPE * e;
    }

    float mx = -1e30f, den = 0.f;
    if (deg > 32) {
        for (int k = beg + 32 + lane; k < end; k += 32) {
            int d2 = g_csr_dst[k];
            float e = sn + g_d[d2];
            e = e > 0.f ? e : NEG_SLOPE * e;
            float mn = fmaxf(mx, e);
            den = den * __expf(mx - mn) + __expf(e - mn);
            mx = mn;
        }
    }
    {
        float mn = fmaxf(mx, ek);
        den = den * __expf(mx - mn) + ((lane < deg) ? __expf(ek - mn) : 0.f);
        mx = mn;
    }
#pragma unroll
    for (int o = 16; o > 0; o >>= 1) {
        float m2 = __shfl_xor_sync(0xffffffffu, mx, o);
        float d2 = __shfl_xor_sync(0xffffffffu, den, o);
        float mn = fmaxf(mx, m2);
        den = den * __expf(mx - mn) + d2 * __expf(m2 - mn);
        mx = mn;
    }
    float inv = (deg > 0) ? 1.0f / den : 0.0f;
    float attk = (lane < deg) ? __expf(ek - mx) * inv : 0.0f;

    float2 acc = make_float2(0.f, 0.f);
    int cnt = min(deg, 32);
    for (int t = 0; t < cnt; t += 8) {
        int dd[8]; float aa[8]; float2 hh[8];
#pragma unroll
        for (int u = 0; u < 8; ++u) {
            dd[u] = __shfl_sync(0xffffffffu, dk, t + u);
            aa[u] = __shfl_sync(0xffffffffu, attk, t + u);
        }
#pragma unroll
        for (int u = 0; u < 8; ++u)
            hh[u] = *(const float2*)(g_Hw1 + dd[u] * HID + lane * 2);
#pragma unroll
        for (int u = 0; u < 8; ++u) {
            acc.x = fmaf(aa[u], hh[u].x, acc.x);
            acc.y = fmaf(aa[u], hh[u].y, acc.y);
        }
    }
    for (int base = beg + 32; base < end; base += 32) {
        int k = base + lane;
        int dk2 = 0; float att2 = 0.f;
        if (k < end) {
            dk2 = g_csr_dst[k];
            float e = sn + g_d[dk2];
            e = e > 0.f ? e : NEG_SLOPE * e;
            att2 = __expf(e - mx) * inv;
        }
        int cnt2 = min(32, end - base);
        for (int t = 0; t < cnt2; t += 8) {
            int dd[8]; float aa[8]; float2 hh[8];
#pragma unroll
            for (int u = 0; u < 8; ++u) {
                dd[u] = __shfl_sync(0xffffffffu, dk2, t + u);
                aa[u] = __shfl_sync(0xffffffffu, att2, t + u);
            }
#pragma unroll
            for (int u = 0; u < 8; ++u)
                hh[u] = *(const float2*)(g_Hw1 + dd[u] * HID + lane * 2);
#pragma unroll
            for (int u = 0; u < 8; ++u) {
                acc.x = fmaf(aa[u], hh[u].x, acc.x);
                acc.y = fmaf(aa[u], hh[u].y, acc.y);
            }
        }
    }
    acc.x = acc.x > 0.f ? acc.x : expm1f(acc.x);
    acc.y = acc.y > 0.f ? acc.y : expm1f(acc.y);

    float o2 = 0.f;
#pragma unroll
    for (int k = 0; k < 32; ++k) {
        float hx = __shfl_sync(0xffffffffu, acc.x, k);
        float hy = __shfl_sync(0xffffffffu, acc.y, k);
        o2 = fmaf(hx, W2s[(2 * k) * CLS + lane], o2);
        o2 = fmaf(hy, W2s[(2 * k + 1) * CLS + lane], o2);
    }
    g_Hw2[n * CLS + lane] = o2;

    float sp = o2 * A2s[lane];
    float dp = o2 * A2s[CLS + lane];
#pragma unroll
    for (int o = 16; o > 0; o >>= 1) {
        sp += __shfl_down_sync(0xffffffffu, sp, o);
        dp += __shfl_down_sync(0xffffffffu, dp, o);
    }
    if (lane == 0) { g_s2[n] = sp; g_d2[n] = dp; }
}

// ================= layer-2 softagg + log_softmax =============================
__global__ void k_softagg32(float* __restrict__ out) {
    int n = blockIdx.x * 8 + (threadIdx.x >> 5);
    int lane = threadIdx.x & 31;
    int beg = seg_beg(n), end = seg_end(n);
    int deg = end - beg;
    float sn = g_s2[n];

    int dk = 0; float ek = -1e30f;
    if (lane < deg) {
        dk = g_csr_dst[beg + lane];
        float e = sn + g_d2[dk];
        ek = e > 0.f ? e : NEG_SLOPE * e;
    }

    float mx = -1e30f, den = 0.f;
    if (deg > 32) {
        for (int k = beg + 32 + lane; k < end; k += 32) {
            int d2 = g_csr_dst[k];
            float e = sn + g_d2[d2];
            e = e > 0.f ? e : NEG_SLOPE * e;
            float mn = fmaxf(mx, e);
            den = den * __expf(mx - mn) + __expf(e - mn);
            mx = mn;
        }
    }
    {
        float mn = fmaxf(mx, ek);
        den = den * __expf(mx - mn) + ((lane < deg) ? __expf(ek - mn) : 0.f);
        mx = mn;
    }
#pragma unroll
    for (int o = 16; o > 0; o >>= 1) {
        float m2 = __shfl_xor_sync(0xffffffffu, mx, o);
        float d2 = __shfl_xor_sync(0xffffffffu, den, o);
        float mn = fmaxf(mx, m2);
        den = den * __expf(mx - mn) + d2 * __expf(m2 - mn);
        mx = mn;
    }
    float inv = (deg > 0) ? 1.0f / den : 0.0f;
    float attk = (lane < deg) ? __expf(ek - mx) * inv : 0.0f;

    float acc = 0.f;
    int cnt = min(deg, 32);
    for (int t = 0; t < cnt; t += 8) {
        int dd[8]; float aa[8]; float hh[8];
#pragma unroll
        for (int u = 0; u < 8; ++u) {
            dd[u] = __shfl_sync(0xffffffffu, dk, t + u);
            aa[u] = __shfl_sync(0xffffffffu, attk, t + u);
        }
#pragma unroll
        for (int u = 0; u < 8; ++u)
            hh[u] = g_Hw2[dd[u] * CLS + lane];
#pragma unroll
        for (int u = 0; u < 8; ++u)
            acc = fmaf(aa[u], hh[u], acc);
    }
    for (int base = beg + 32; base < end; base += 32) {
        int k = base + lane;
        int dk2 = 0; float att2 = 0.f;
        if (k < end) {
            dk2 = g_csr_dst[k];
            float e = sn + g_d2[dk2];
            e = e > 0.f ? e : NEG_SLOPE * e;
            att2 = __expf(e - mx) * inv;
        }
        int cnt2 = min(32, end - base);
        for (int t = 0; t < cnt2; t += 8) {
            int dd[8]; float aa[8]; float hh[8];
#pragma unroll
            for (int u = 0; u < 8; ++u) {
                dd[u] = __shfl_sync(0xffffffffu, dk2, t + u);
                aa[u] = __shfl_sync(0xffffffffu, att2, t + u);
            }
#pragma unroll
            for (int u = 0; u < 8; ++u)
                hh[u] = g_Hw2[dd[u] * CLS + lane];
#pragma unroll
            for (int u = 0; u < 8; ++u)
                acc = fmaf(aa[u], hh[u], acc);
        }
    }
    float m2 = acc;
#pragma unroll
    for (int o = 16; o > 0; o >>= 1) m2 = fmaxf(m2, __shfl_xor_sync(0xffffffffu, m2, o));
    float ex = __expf(acc - m2);
    float sm = ex;
#pragma unroll
    for (int o = 16; o > 0; o >>= 1) sm += __shfl_xor_sync(0xffffffffu, sm, o);
    out[n * CLS + lane] = acc - m2 - __logf(sm);
}

// ================= launch ====================================================
extern "C" void kernel_launch(void* const* d_in, const int* in_sizes, int n_in,
                              void* d_out, int out_size) {
    const float* X  = (const float*)d_in[0];
    const int*   EI = (const int*)d_in[1];
    const float* W1 = (const float*)d_in[2];
    const float* W2 = (const float*)d_in[3];
    const float* A1 = (const float*)d_in[4];
    const float* A2 = (const float*)d_in[5];
    float* out = (float*)d_out;

    // one-time resource creation (host-side only; no device memory)
    static cudaStream_t s_side = nullptr;
    static cudaEvent_t  ev_fork = nullptr, ev_join = nullptr;
    if (!s_side) {
        cudaStreamCreateWithFlags(&s_side, cudaStreamNonBlocking);
        cudaEventCreateWithFlags(&ev_fork, cudaEventDisableTiming);
        cudaEventCreateWithFlags(&ev_join, cudaEventDisableTiming);
        cudaFuncSetAttribute(k_gemm1_mma,
                             cudaFuncAttributeMaxDynamicSharedMemorySize, GEMM1_SMEM);
    }

    const int T = 256;
    int g_nodes = (N_NODES + T - 1) / T;       // 391
    int g_edges = (N_EDGES + T - 1) / T;       // 6250

    // fork: CSR chain on side stream, GEMM chain on main stream
    cudaEventRecord(ev_fork, 0);
    cudaStreamWaitEvent(s_side, ev_fork, 0);

    k_zero <<<g_nodes, T, 0, s_side>>>();
    k_count<<<g_edges, T, 0, s_side>>>(EI);
    k_scan1<<<NBLK_SCAN, 256, 0, s_side>>>();
    k_scan2<<<1, 512, 0, s_side>>>();
    k_fill <<<g_edges, T, 0, s_side>>>(EI);
    cudaEventRecord(ev_join, s_side);

    k_packW<<<16, 256>>>(W1);
    k_gemm1_mma<<<(N_NODES + BM - 1) / BM, 256, GEMM1_SMEM>>>(X, A1);

    // join: softagg needs both CSR and gemm1 results
    cudaStreamWaitEvent(0, ev_join, 0);
    k_softagg64g2<<<N_NODES / 16, 512>>>(W2, A2);
    k_softagg32<<<N_NODES / 8, 256>>>(out);
}

// round 11
// speedup vs baseline: 1.0094x; 1.0094x over previous
#include <cuda_runtime.h>
#include <cuda_bf16.h>
#include <math.h>
#include <stdint.h>

#define N_NODES   100000
#define N_EDGES   1600000
#define IN_DIM    256
#define HID       64
#define CLS       32
#define NEG_SLOPE 0.01f
#define NBLK_SCAN ((N_NODES + 255) / 256)   // 391

#define BM      128
#define KCHUNK  128
#define KPAD    136
#define GEMM1_SMEM (2 * BM * KPAD * 2)      // 69632 B
#define NGEMM   ((N_NODES + BM - 1) / BM)   // 782
#define NCOUNT  ((N_EDGES + 255) / 256)     // 6250

// ---------------- scratch (device globals; no allocations allowed) ----------
__device__ float    g_Hw1[N_NODES * HID];
__device__ float    g_Hw2[N_NODES * CLS];
__device__ float    g_s[N_NODES];            // layer-1 scores
__device__ float    g_d[N_NODES];
__device__ float    g_s2[N_NODES];           // layer-2 scores
__device__ float    g_d2[N_NODES];
__device__ int      g_deg[N_NODES];
__device__ int      g_off[N_NODES];          // within-block exclusive scan
__device__ int      g_pos[N_NODES];
__device__ int      g_csr_dst[N_EDGES];
__device__ int      g_bsum[NBLK_SCAN];
__device__ int      g_bscan[NBLK_SCAN];
__device__ uint32_t g_Wpack[2 * 16 * 8 * 32 * 2];

__device__ __forceinline__ int seg_beg(int n) {
    return g_off[n] + g_bscan[n >> 8];
}
__device__ __forceinline__ int seg_end(int n) {
    return (n + 1 < N_NODES) ? (g_off[n + 1] + g_bscan[(n + 1) >> 8]) : N_EDGES;
}

// ================= init: zero counters + pack W1 (bf16 hi/lo B-frags) ========
__global__ void k_init_pack(const float* __restrict__ W1) {
    int idx = blockIdx.x * blockDim.x + threadIdx.x;
    if (idx < N_NODES) { g_deg[idx] = 0; g_pos[idx] = 0; }
    if (idx < 4096) {
        int ks   = idx >> 8;
        int nb   = (idx >> 5) & 7;
        int lane = idx & 31;
        int n  = nb * 8 + (lane >> 2);
        int k0 = ks * 16 + (lane & 3) * 2;
#pragma unroll
        for (int r = 0; r < 2; ++r) {
            int k = k0 + r * 8;
            float w0 = W1[k * HID + n];
            float w1 = W1[(k + 1) * HID + n];
            __nv_bfloat162 h = __float22bfloat162_rn(make_float2(w0, w1));
            __nv_bfloat162 l = __float22bfloat162_rn(
                make_float2(w0 - __low2float(h), w1 - __high2float(h)));
            g_Wpack[((0 * 16 + ks) * 8 + nb) * 64 + lane * 2 + r] = *(uint32_t*)&h;
            g_Wpack[((1 * 16 + ks) * 8 + nb) * 64 + lane * 2 + r] = *(uint32_t*)&l;
        }
    }
}

// ================= CSR scan + fill ==========================================
__global__ void k_scan1() {
    __shared__ int sh[256];
    int t = threadIdx.x;
    int i = blockIdx.x * 256 + t;
    int v = (i < N_NODES) ? g_deg[i] : 0;
    sh[t] = v;
    __syncthreads();
#pragma unroll
    for (int o = 1; o < 256; o <<= 1) {
        int x = (t >= o) ? sh[t - o] : 0;
        __syncthreads();
        sh[t] += x;
        __syncthreads();
    }
    if (i < N_NODES) g_off[i] = sh[t] - v;
    if (t == 255) g_bsum[blockIdx.x] = sh[255];
}

__global__ void k_scan2() {
    __shared__ int sh[512];
    int t = threadIdx.x;
    int v = (t < NBLK_SCAN) ? g_bsum[t] : 0;
    sh[t] = v;
    __syncthreads();
#pragma unroll
    for (int o = 1; o < 512; o <<= 1) {
        int x = (t >= o) ? sh[t - o] : 0;
        __syncthreads();
        sh[t] += x;
        __syncthreads();
    }
    if (t < NBLK_SCAN) g_bscan[t] = sh[t] - v;
}

__global__ void k_fill(const int* __restrict__ ei) {
    int i = blockIdx.x * blockDim.x + threadIdx.x;
    if (i >= N_EDGES) return;
    int s = ei[i];
    int slot = seg_beg(s) + atomicAdd(&g_pos[s], 1);
    g_csr_dst[slot] = ei[N_EDGES + i];
}

// ================= MEGA: layer-1 GEMM blocks + degree-count blocks ===========
__device__ __forceinline__ void mma16816(float* c, uint32_t a0, uint32_t a1,
                                         uint32_t a2, uint32_t a3,
                                         uint32_t b0, uint32_t b1) {
    asm volatile(
        "mma.sync.aligned.m16n8k16.row.col.f32.bf16.bf16.f32 "
        "{%0,%1,%2,%3}, {%4,%5,%6,%7}, {%8,%9}, {%0,%1,%2,%3};\n"
        : "+f"(c[0]), "+f"(c[1]), "+f"(c[2]), "+f"(c[3])
        : "r"(a0), "r"(a1), "r"(a2), "r"(a3), "r"(b0), "r"(b1));
}

__global__ __launch_bounds__(256) void k_mega(const float* __restrict__ X,
                                              const float* __restrict__ A1,
                                              const int* __restrict__ ei) {
    // ---- count path: blocks beyond the GEMM range do degree counting ----
    if (blockIdx.x >= NGEMM) {
        int i = (blockIdx.x - NGEMM) * 256 + threadIdx.x;
        if (i < N_EDGES) atomicAdd(&g_deg[ei[i]], 1);
        return;
    }

    // ---- gemm path ----
    extern __shared__ unsigned short sm[];
    unsigned short* Ahi = sm;
    unsigned short* Alo = sm + BM * KPAD;

    int tid  = threadIdx.x;
    int warp = tid >> 5;
    int lane = tid & 31;
    int row0 = blockIdx.x * BM;

    float acc[8][4];
#pragma unroll
    for (int nb = 0; nb < 8; ++nb)
#pragma unroll
        for (int r = 0; r < 4; ++r) acc[nb][r] = 0.f;

    for (int chunk = 0; chunk < IN_DIM / KCHUNK; ++chunk) {
        __syncthreads();
        for (int i = tid; i < BM * (KCHUNK / 4); i += 256) {
            int r  = i >> 5;
            int c4 = i & 31;
            float4 v = make_float4(0.f, 0.f, 0.f, 0.f);
            if (row0 + r < N_NODES)
                v = __ldg((const float4*)(X + (size_t)(row0 + r) * IN_DIM
                                            + chunk * KCHUNK + c4 * 4));
            __nv_bfloat162 h01 = __float22bfloat162_rn(make_float2(v.x, v.y));
            __nv_bfloat162 h23 = __float22bfloat162_rn(make_float2(v.z, v.w));
            __nv_bfloat162 l01 = __float22bfloat162_rn(
                make_float2(v.x - __low2float(h01), v.y - __high2float(h01)));
            __nv_bfloat162 l23 = __float22bfloat162_rn(
                make_float2(v.z - __low2float(h23), v.w - __high2float(h23)));
            uint32_t base = r * KPAD + c4 * 4;
            *(uint32_t*)(Ahi + base)     = *(uint32_t*)&h01;
            *(uint32_t*)(Ahi + base + 2) = *(uint32_t*)&h23;
            *(uint32_t*)(Alo + base)     = *(uint32_t*)&l01;
            *(uint32_t*)(Alo + base + 2) = *(uint32_t*)&l23;
        }
        __syncthreads();

        int rA = warp * 16 + (lane >> 2);
#pragma unroll
        for (int ks = 0; ks < KCHUNK / 16; ++ks) {
            int kc = ks * 16 + (lane & 3) * 2;
            uint32_t ah0 = *(uint32_t*)(Ahi + rA * KPAD + kc);
            uint32_t ah1 = *(uint32_t*)(Ahi + (rA + 8) * KPAD + kc);
            uint32_t ah2 = *(uint32_t*)(Ahi + rA * KPAD + kc + 8);
            uint32_t ah3 = *(uint32_t*)(Ahi + (rA + 8) * KPAD + kc + 8);
            uint32_t al0 = *(uint32_t*)(Alo + rA * KPAD + kc);
            uint32_t al1 = *(uint32_t*)(Alo + (rA + 8) * KPAD + kc);
            uint32_t al2 = *(uint32_t*)(Alo + rA * KPAD + kc + 8);
            uint32_t al3 = *(uint32_t*)(Alo + (rA + 8) * KPAD + kc + 8);
            int ksg = chunk * (KCHUNK / 16) + ks;
#pragma unroll
            for (int nb = 0; nb < 8; ++nb) {
                uint2 bh = __ldg((const uint2*)(g_Wpack + ((0 * 16 + ksg) * 8 + nb) * 64 + lane * 2));
                uint2 bl = __ldg((const uint2*)(g_Wpack + ((1 * 16 + ksg) * 8 + nb) * 64 + lane * 2));
                mma16816(acc[nb], ah0, ah1, ah2, ah3, bh.x, bh.y);
                mma16816(acc[nb], ah0, ah1, ah2, ah3, bl.x, bl.y);
                mma16816(acc[nb], al0, al1, al2, al3, bh.x, bh.y);
            }
        }
    }

    int rowA = row0 + warp * 16 + (lane >> 2);
    int colA = (lane & 3) * 2;
#pragma unroll
    for (int nb = 0; nb < 8; ++nb) {
        int col = nb * 8 + colA;
        if (rowA < N_NODES)
            *(float2*)(g_Hw1 + (size_t)rowA * HID + col) = make_float2(acc[nb][0], acc[nb][1]);
        if (rowA + 8 < N_NODES)
            *(float2*)(g_Hw1 + (size_t)(rowA + 8) * HID + col) = make_float2(acc[nb][2], acc[nb][3]);
    }

    float s0 = 0.f, d0 = 0.f, s1 = 0.f, d1 = 0.f;
#pragma unroll
    for (int nb = 0; nb < 8; ++nb) {
        int col = nb * 8 + colA;
        float a0 = __ldg(&A1[col]),       a1 = __ldg(&A1[col + 1]);
        float b0 = __ldg(&A1[HID + col]), b1 = __ldg(&A1[HID + col + 1]);
        s0 += acc[nb][0] * a0 + acc[nb][1] * a1;
        d0 += acc[nb][0] * b0 + acc[nb][1] * b1;
        s1 += acc[nb][2] * a0 + acc[nb][3] * a1;
        d1 += acc[nb][2] * b0 + acc[nb][3] * b1;
    }
#pragma unroll
    for (int o = 1; o <= 2; o <<= 1) {
        s0 += __shfl_xor_sync(0xffffffffu, s0, o);
        d0 += __shfl_xor_sync(0xffffffffu, d0, o);
        s1 += __shfl_xor_sync(0xffffffffu, s1, o);
        d1 += __shfl_xor_sync(0xffffffffu, d1, o);
    }
    if ((lane & 3) == 0) {
        if (rowA < N_NODES)     { g_s[rowA] = s0;     g_d[rowA] = d0; }
        if (rowA + 8 < N_NODES) { g_s[rowA + 8] = s1; g_d[rowA + 8] = d1; }
    }
}

// ================= layer-1 softagg + ELU + fused gemm2 + scores ==============
__global__ __launch_bounds__(512) void k_softagg64g2(const float* __restrict__ W2,
                                                     const float* __restrict__ A2) {
    __shared__ float W2s[HID * CLS];     // 8 KB
    __shared__ float A2s[2 * CLS];
    for (int i = threadIdx.x; i < HID * CLS; i += 512) W2s[i] = W2[i];
    if (threadIdx.x < 2 * CLS) A2s[threadIdx.x] = A2[threadIdx.x];
    __syncthreads();

    int n = blockIdx.x * 16 + (threadIdx.x >> 5);
    int lane = threadIdx.x & 31;
    int beg = seg_beg(n), end = seg_end(n);
    int deg = end - beg;
    float sn = g_s[n];

    int dk = 0; float ek = -1e30f;
    if (lane < deg) {
        dk = g_csr_dst[beg + lane];
        float e = sn + g_d[dk];
        ek = e > 0.f ? e : NEG_SLOPE * e;
    }

    float mx = -1e30f, den = 0.f;
    if (deg > 32) {
        for (int k = beg + 32 + lane; k < end; k += 32) {
            int d2 = g_csr_dst[k];
            float e = sn + g_d[d2];
            e = e > 0.f ? e : NEG_SLOPE * e;
            float mn = fmaxf(mx, e);
            den = den * __expf(mx - mn) + __expf(e - mn);
            mx = mn;
        }
    }
    {
        float mn = fmaxf(mx, ek);
        den = den * __expf(mx - mn) + ((lane < deg) ? __expf(ek - mn) : 0.f);
        mx = mn;
    }
#pragma unroll
    for (int o = 16; o > 0; o >>= 1) {
        float m2 = __shfl_xor_sync(0xffffffffu, mx, o);
        float d2 = __shfl_xor_sync(0xffffffffu, den, o);
        float mn = fmaxf(mx, m2);
        den = den * __expf(mx - mn) + d2 * __expf(m2 - mn);
        mx = mn;
    }
    float inv = (deg > 0) ? 1.0f / den : 0.0f;
    float attk = (lane < deg) ? __expf(ek - mx) * inv : 0.0f;

    float2 acc = make_float2(0.f, 0.f);
    int cnt = min(deg, 32);
    for (int t = 0; t < cnt; t += 8) {
        int dd[8]; float aa[8]; float2 hh[8];
#pragma unroll
        for (int u = 0; u < 8; ++u) {
            dd[u] = __shfl_sync(0xffffffffu, dk, t + u);
            aa[u] = __shfl_sync(0xffffffffu, attk, t + u);
        }
#pragma unroll
        for (int u = 0; u < 8; ++u)
            hh[u] = *(const float2*)(g_Hw1 + dd[u] * HID + lane * 2);
#pragma unroll
        for (int u = 0; u < 8; ++u) {
            acc.x = fmaf(aa[u], hh[u].x, acc.x);
            acc.y = fmaf(aa[u], hh[u].y, acc.y);
        }
    }
    for (int base = beg + 32; base < end; base += 32) {
        int k = base + lane;
        int dk2 = 0; float att2 = 0.f;
        if (k < end) {
            dk2 = g_csr_dst[k];
            float e = sn + g_d[dk2];
            e = e > 0.f ? e : NEG_SLOPE * e;
            att2 = __expf(e - mx) * inv;
        }
        int cnt2 = min(32, end - base);
        for (int t = 0; t < cnt2; t += 8) {
            int dd[8]; float aa[8]; float2 hh[8];
#pragma unroll
            for (int u = 0; u < 8; ++u) {
                dd[u] = __shfl_sync(0xffffffffu, dk2, t + u);
                aa[u] = __shfl_sync(0xffffffffu, att2, t + u);
            }
#pragma unroll
            for (int u = 0; u < 8; ++u)
                hh[u] = *(const float2*)(g_Hw1 + dd[u] * HID + lane * 2);
#pragma unroll
            for (int u = 0; u < 8; ++u) {
                acc.x = fmaf(aa[u], hh[u].x, acc.x);
                acc.y = fmaf(aa[u], hh[u].y, acc.y);
            }
        }
    }
    acc.x = acc.x > 0.f ? acc.x : expm1f(acc.x);
    acc.y = acc.y > 0.f ? acc.y : expm1f(acc.y);

    float o2 = 0.f;
#pragma unroll
    for (int k = 0; k < 32; ++k) {
        float hx = __shfl_sync(0xffffffffu, acc.x, k);
        float hy = __shfl_sync(0xffffffffu, acc.y, k);
        o2 = fmaf(hx, W2s[(2 * k) * CLS + lane], o2);
        o2 = fmaf(hy, W2s[(2 * k + 1) * CLS + lane], o2);
    }
    g_Hw2[n * CLS + lane] = o2;

    float sp = o2 * A2s[lane];
    float dp = o2 * A2s[CLS + lane];
#pragma unroll
    for (int o = 16; o > 0; o >>= 1) {
        sp += __shfl_down_sync(0xffffffffu, sp, o);
        dp += __shfl_down_sync(0xffffffffu, dp, o);
    }
    if (lane == 0) { g_s2[n] = sp; g_d2[n] = dp; }
}

// ================= layer-2 softagg + log_softmax =============================
__global__ void k_softagg32(float* __restrict__ out) {
    int n = blockIdx.x * 8 + (threadIdx.x >> 5);
    int lane = threadIdx.x & 31;
    int beg = seg_beg(n), end = seg_end(n);
    int deg = end - beg;
    float sn = g_s2[n];

    int dk = 0; float ek = -1e30f;
    if (lane < deg) {
        dk = g_csr_dst[beg + lane];
        float e = sn + g_d2[dk];
        ek = e > 0.f ? e : NEG_SLOPE * e;
    }

    float mx = -1e30f, den = 0.f;
    if (deg > 32) {
        for (int k = beg + 32 + lane; k < end; k += 32) {
            int d2 = g_csr_dst[k];
            float e = sn + g_d2[d2];
            e = e > 0.f ? e : NEG_SLOPE * e;
            float mn = fmaxf(mx, e);
            den = den * __expf(mx - mn) + __expf(e - mn);
            mx = mn;
        }
    }
    {
        float mn = fmaxf(mx, ek);
        den = den * __expf(mx - mn) + ((lane < deg) ? __expf(ek - mn) : 0.f);
        mx = mn;
    }
#pragma unroll
    for (int o = 16; o > 0; o >>= 1) {
        float m2 = __shfl_xor_sync(0xffffffffu, mx, o);
        float d2 = __shfl_xor_sync(0xffffffffu, den, o);
        float mn = fmaxf(mx, m2);
        den = den * __expf(mx - mn) + d2 * __expf(m2 - mn);
        mx = mn;
    }
    float inv = (deg > 0) ? 1.0f / den : 0.0f;
    float attk = (lane < deg) ? __expf(ek - mx) * inv : 0.0f;

    float acc = 0.f;
    int cnt = min(deg, 32);
    for (int t = 0; t < cnt; t += 8) {
        int dd[8]; float aa[8]; float hh[8];
#pragma unroll
        for (int u = 0; u < 8; ++u) {
            dd[u] = __shfl_sync(0xffffffffu, dk, t + u);
            aa[u] = __shfl_sync(0xffffffffu, attk, t + u);
        }
#pragma unroll
        for (int u = 0; u < 8; ++u)
            hh[u] = g_Hw2[dd[u] * CLS + lane];
#pragma unroll
        for (int u = 0; u < 8; ++u)
            acc = fmaf(aa[u], hh[u], acc);
    }
    for (int base = beg + 32; base < end; base += 32) {
        int k = base + lane;
        int dk2 = 0; float att2 = 0.f;
        if (k < end) {
            dk2 = g_csr_dst[k];
            float e = sn + g_d2[dk2];
            e = e > 0.f ? e : NEG_SLOPE * e;
            att2 = __expf(e - mx) * inv;
        }
        int cnt2 = min(32, end - base);
        for (int t = 0; t < cnt2; t += 8) {
            int dd[8]; float aa[8]; float hh[8];
#pragma unroll
            for (int u = 0; u < 8; ++u) {
                dd[u] = __shfl_sync(0xffffffffu, dk2, t + u);
                aa[u] = __shfl_sync(0xffffffffu, att2, t + u);
            }
#pragma unroll
            for (int u = 0; u < 8; ++u)
                hh[u] = g_Hw2[dd[u] * CLS + lane];
#pragma unroll
            for (int u = 0; u < 8; ++u)
                acc = fmaf(aa[u], hh[u], acc);
        }
    }
    float m2 = acc;
#pragma unroll
    for (int o = 16; o > 0; o >>= 1) m2 = fmaxf(m2, __shfl_xor_sync(0xffffffffu, m2, o));
    float ex = __expf(acc - m2);
    float sm = ex;
#pragma unroll
    for (int o = 16; o > 0; o >>= 1) sm += __shfl_xor_sync(0xffffffffu, sm, o);
    out[n * CLS + lane] = acc - m2 - __logf(sm);
}

// ================= launch ====================================================
extern "C" void kernel_launch(void* const* d_in, const int* in_sizes, int n_in,
                              void* d_out, int out_size) {
    const float* X  = (const float*)d_in[0];
    const int*   EI = (const int*)d_in[1];
    const float* W1 = (const float*)d_in[2];
    const float* W2 = (const float*)d_in[3];
    const float* A1 = (const float*)d_in[4];
    const float* A2 = (const float*)d_in[5];
    float* out = (float*)d_out;

    static bool s_init = false;
    if (!s_init) {
        cudaFuncSetAttribute(k_mega,
                             cudaFuncAttributeMaxDynamicSharedMemorySize, GEMM1_SMEM);
        s_init = true;
    }

    const int T = 256;
    int g_nodes = (N_NODES + T - 1) / T;       // 391
    int g_edges = (N_EDGES + T - 1) / T;       // 6250

    k_init_pack<<<g_nodes, T>>>(W1);
    // mega: 782 gemm blocks + 6250 count blocks in ONE wave (overlap by scheduler)
    k_mega<<<NGEMM + NCOUNT, 256, GEMM1_SMEM>>>(X, A1, EI);
    k_scan1<<<NBLK_SCAN, 256>>>();
    k_scan2<<<1, 512>>>();
    k_fill<<<g_edges, T>>>(EI);

    k_softagg64g2<<<N_NODES / 16, 512>>>(W2, A2);
    k_softagg32<<<N_NODES / 8, 256>>>(out);
}

// round 12
// speedup vs baseline: 1.0809x; 1.0708x over previous
#include <cuda_runtime.h>
#include <cuda_bf16.h>
#include <cuda_fp16.h>
#include <math.h>
#include <stdint.h>

#define N_NODES   100000
#define N_EDGES   1600000
#define IN_DIM    256
#define HID       64
#define CLS       32
#define NEG_SLOPE 0.01f
#define NBLK_SCAN ((N_NODES + 255) / 256)   // 391

#define BM      128
#define KCHUNK  128
#define KPAD    136
#define GEMM1_SMEM (2 * BM * KPAD * 2)      // 69632 B

// ---------------- scratch (device globals; no allocations allowed) ----------
__device__ __half   g_Hw1h[N_NODES * HID];   // layer-1 features (fp16, 12.8 MB)
__device__ float    g_Hw2[N_NODES * CLS];
__device__ float    g_s[N_NODES];            // layer-1 scores
__device__ float    g_d[N_NODES];
__device__ float    g_s2[N_NODES];           // layer-2 scores
__device__ float    g_d2[N_NODES];
__device__ int      g_deg[N_NODES];
__device__ int      g_off[N_NODES];          // within-block exclusive scan
__device__ int      g_pos[N_NODES];
__device__ int      g_csr_dst[N_EDGES];
__device__ int      g_bsum[NBLK_SCAN];
__device__ int      g_bscan[NBLK_SCAN];
__device__ uint32_t g_Wpack[2 * 16 * 8 * 32 * 2];

__device__ __forceinline__ int seg_beg(int n) {
    return g_off[n] + g_bscan[n >> 8];
}
__device__ __forceinline__ int seg_end(int n) {
    return (n + 1 < N_NODES) ? (g_off[n + 1] + g_bscan[(n + 1) >> 8]) : N_EDGES;
}

// ================= init: zero counters + pack W1 (bf16 hi/lo B-frags) ========
__global__ void k_init_pack(const float* __restrict__ W1) {
    int idx = blockIdx.x * blockDim.x + threadIdx.x;
    if (idx < N_NODES) { g_deg[idx] = 0; g_pos[idx] = 0; }
    if (idx < 4096) {
        int ks   = idx >> 8;
        int nb   = (idx >> 5) & 7;
        int lane = idx & 31;
        int n  = nb * 8 + (lane >> 2);
        int k0 = ks * 16 + (lane & 3) * 2;
#pragma unroll
        for (int r = 0; r < 2; ++r) {
            int k = k0 + r * 8;
            float w0 = W1[k * HID + n];
            float w1 = W1[(k + 1) * HID + n];
            __nv_bfloat162 h = __float22bfloat162_rn(make_float2(w0, w1));
            __nv_bfloat162 l = __float22bfloat162_rn(
                make_float2(w0 - __low2float(h), w1 - __high2float(h)));
            g_Wpack[((0 * 16 + ks) * 8 + nb) * 64 + lane * 2 + r] = *(uint32_t*)&h;
            g_Wpack[((1 * 16 + ks) * 8 + nb) * 64 + lane * 2 + r] = *(uint32_t*)&l;
        }
    }
}

// ================= CSR build =================================================
__global__ void k_count(const int* __restrict__ ei) {
    int i = blockIdx.x * blockDim.x + threadIdx.x;
    if (i < N_EDGES) atomicAdd(&g_deg[ei[i]], 1);
}

__global__ void k_scan1() {
    __shared__ int sh[256];
    int t = threadIdx.x;
    int i = blockIdx.x * 256 + t;
    int v = (i < N_NODES) ? g_deg[i] : 0;
    sh[t] = v;
    __syncthreads();
#pragma unroll
    for (int o = 1; o < 256; o <<= 1) {
        int x = (t >= o) ? sh[t - o] : 0;
        __syncthreads();
        sh[t] += x;
        __syncthreads();
    }
    if (i < N_NODES) g_off[i] = sh[t] - v;
    if (t == 255) g_bsum[blockIdx.x] = sh[255];
}

__global__ void k_scan2() {
    __shared__ int sh[512];
    int t = threadIdx.x;
    int v = (t < NBLK_SCAN) ? g_bsum[t] : 0;
    sh[t] = v;
    __syncthreads();
#pragma unroll
    for (int o = 1; o < 512; o <<= 1) {
        int x = (t >= o) ? sh[t - o] : 0;
        __syncthreads();
        sh[t] += x;
        __syncthreads();
    }
    if (t < NBLK_SCAN) g_bscan[t] = sh[t] - v;
}

__global__ void k_fill(const int* __restrict__ ei) {
    int i = blockIdx.x * blockDim.x + threadIdx.x;
    if (i >= N_EDGES) return;
    int s = ei[i];
    int slot = seg_beg(s) + atomicAdd(&g_pos[s], 1);
    g_csr_dst[slot] = ei[N_EDGES + i];
}

// ================= layer-1 GEMM (tensor cores, bf16 split) + scores ==========
__device__ __forceinline__ void mma16816(float* c, uint32_t a0, uint32_t a1,
                                         uint32_t a2, uint32_t a3,
                                         uint32_t b0, uint32_t b1) {
    asm volatile(
        "mma.sync.aligned.m16n8k16.row.col.f32.bf16.bf16.f32 "
        "{%0,%1,%2,%3}, {%4,%5,%6,%7}, {%8,%9}, {%0,%1,%2,%3};\n"
        : "+f"(c[0]), "+f"(c[1]), "+f"(c[2]), "+f"(c[3])
        : "r"(a0), "r"(a1), "r"(a2), "r"(a3), "r"(b0), "r"(b1));
}

__global__ __launch_bounds__(256) void k_gemm1_mma(const float* __restrict__ X,
                                                   const float* __restrict__ A1) {
    extern __shared__ unsigned short sm[];
    unsigned short* Ahi = sm;
    unsigned short* Alo = sm + BM * KPAD;

    int tid  = threadIdx.x;
    int warp = tid >> 5;
    int lane = tid & 31;
    int row0 = blockIdx.x * BM;

    float acc[8][4];
#pragma unroll
    for (int nb = 0; nb < 8; ++nb)
#pragma unroll
        for (int r = 0; r < 4; ++r) acc[nb][r] = 0.f;

    for (int chunk = 0; chunk < IN_DIM / KCHUNK; ++chunk) {
        __syncthreads();
        for (int i = tid; i < BM * (KCHUNK / 4); i += 256) {
            int r  = i >> 5;
            int c4 = i & 31;
            float4 v = make_float4(0.f, 0.f, 0.f, 0.f);
            if (row0 + r < N_NODES)
                v = __ldg((const float4*)(X + (size_t)(row0 + r) * IN_DIM
                                            + chunk * KCHUNK + c4 * 4));
            __nv_bfloat162 h01 = __float22bfloat162_rn(make_float2(v.x, v.y));
            __nv_bfloat162 h23 = __float22bfloat162_rn(make_float2(v.z, v.w));
            __nv_bfloat162 l01 = __float22bfloat162_rn(
                make_float2(v.x - __low2float(h01), v.y - __high2float(h01)));
            __nv_bfloat162 l23 = __float22bfloat162_rn(
                make_float2(v.z - __low2float(h23), v.w - __high2float(h23)));
            uint32_t base = r * KPAD + c4 * 4;
            *(uint32_t*)(Ahi + base)     = *(uint32_t*)&h01;
            *(uint32_t*)(Ahi + base + 2) = *(uint32_t*)&h23;
            *(uint32_t*)(Alo + base)     = *(uint32_t*)&l01;
            *(uint32_t*)(Alo + base + 2) = *(uint32_t*)&l23;
        }
        __syncthreads();

        int rA = warp * 16 + (lane >> 2);
#pragma unroll
        for (int ks = 0; ks < KCHUNK / 16; ++ks) {
            int kc = ks * 16 + (lane & 3) * 2;
            uint32_t ah0 = *(uint32_t*)(Ahi + rA * KPAD + kc);
            uint32_t ah1 = *(uint32_t*)(Ahi + (rA + 8) * KPAD + kc);
            uint32_t ah2 = *(uint32_t*)(Ahi + rA * KPAD + kc + 8);
            uint32_t ah3 = *(uint32_t*)(Ahi + (rA + 8) * KPAD + kc + 8);
            uint32_t al0 = *(uint32_t*)(Alo + rA * KPAD + kc);
            uint32_t al1 = *(uint32_t*)(Alo + (rA + 8) * KPAD + kc);
            uint32_t al2 = *(uint32_t*)(Alo + rA * KPAD + kc + 8);
            uint32_t al3 = *(uint32_t*)(Alo + (rA + 8) * KPAD + kc + 8);
            int ksg = chunk * (KCHUNK / 16) + ks;
#pragma unroll
            for (int nb = 0; nb < 8; ++nb) {
                uint2 bh = __ldg((const uint2*)(g_Wpack + ((0 * 16 + ksg) * 8 + nb) * 64 + lane * 2));
                uint2 bl = __ldg((const uint2*)(g_Wpack + ((1 * 16 + ksg) * 8 + nb) * 64 + lane * 2));
                mma16816(acc[nb], ah0, ah1, ah2, ah3, bh.x, bh.y);
                mma16816(acc[nb], ah0, ah1, ah2, ah3, bl.x, bl.y);
                mma16816(acc[nb], al0, al1, al2, al3, bh.x, bh.y);
            }
        }
    }

    int rowA = row0 + warp * 16 + (lane >> 2);
    int colA = (lane & 3) * 2;
#pragma unroll
    for (int nb = 0; nb < 8; ++nb) {
        int col = nb * 8 + colA;
        if (rowA < N_NODES)
            *(__half2*)(g_Hw1h + (size_t)rowA * HID + col) =
                __floats2half2_rn(acc[nb][0], acc[nb][1]);
        if (rowA + 8 < N_NODES)
            *(__half2*)(g_Hw1h + (size_t)(rowA + 8) * HID + col) =
                __floats2half2_rn(acc[nb][2], acc[nb][3]);
    }

    // fused attention scores (fp32 accumulators — unaffected by fp16 storage)
    float s0 = 0.f, d0 = 0.f, s1 = 0.f, d1 = 0.f;
#pragma unroll
    for (int nb = 0; nb < 8; ++nb) {
        int col = nb * 8 + colA;
        float a0 = __ldg(&A1[col]),       a1 = __ldg(&A1[col + 1]);
        float b0 = __ldg(&A1[HID + col]), b1 = __ldg(&A1[HID + col + 1]);
        s0 += acc[nb][0] * a0 + acc[nb][1] * a1;
        d0 += acc[nb][0] * b0 + acc[nb][1] * b1;
        s1 += acc[nb][2] * a0 + acc[nb][3] * a1;
        d1 += acc[nb][2] * b0 + acc[nb][3] * b1;
    }
#pragma unroll
    for (int o = 1; o <= 2; o <<= 1) {
        s0 += __shfl_xor_sync(0xffffffffu, s0, o);
        d0 += __shfl_xor_sync(0xffffffffu, d0, o);
        s1 += __shfl_xor_sync(0xffffffffu, s1, o);
        d1 += __shfl_xor_sync(0xffffffffu, d1, o);
    }
    if ((lane & 3) == 0) {
        if (rowA < N_NODES)     { g_s[rowA] = s0;     g_d[rowA] = d0; }
        if (rowA + 8 < N_NODES) { g_s[rowA + 8] = s1; g_d[rowA + 8] = d1; }
    }
}

// ================= layer-1 softagg + ELU + fused gemm2 + scores ==============
// 256 threads = 8 nodes/block (the round-9 shape; 512 regressed).
__global__ void k_softagg64g2(const float* __restrict__ W2,
                              const float* __restrict__ A2) {
    __shared__ float W2s[HID * CLS];     // 8 KB
    __shared__ float A2s[2 * CLS];
    for (int i = threadIdx.x; i < HID * CLS; i += 256) W2s[i] = W2[i];
    if (threadIdx.x < 2 * CLS) A2s[threadIdx.x] = A2[threadIdx.x];
    __syncthreads();

    int n = blockIdx.x * 8 + (threadIdx.x >> 5);
    int lane = threadIdx.x & 31;
    int beg = seg_beg(n), end = seg_end(n);
    int deg = end - beg;
    float sn = g_s[n];

    int dk = 0; float ek = -1e30f;
    if (lane < deg) {
        dk = g_csr_dst[beg + lane];
        float e = sn + g_d[dk];
        ek = e > 0.f ? e : NEG_SLOPE * e;
    }

    float mx = -1e30f, den = 0.f;
    if (deg > 32) {
        for (int k = beg + 32 + lane; k < end; k += 32) {
            int d2 = g_csr_dst[k];
            float e = sn + g_d[d2];
            e = e > 0.f ? e : NEG_SLOPE * e;
            float mn = fmaxf(mx, e);
            den = den * __expf(mx - mn) + __expf(e - mn);
            mx = mn;
        }
    }
    {
        float mn = fmaxf(mx, ek);
        den = den * __expf(mx - mn) + ((lane < deg) ? __expf(ek - mn) : 0.f);
        mx = mn;
    }
#pragma unroll
    for (int o = 16; o > 0; o >>= 1) {
        float m2 = __shfl_xor_sync(0xffffffffu, mx, o);
        float d2 = __shfl_xor_sync(0xffffffffu, den, o);
        float mn = fmaxf(mx, m2);
        den = den * __expf(mx - mn) + d2 * __expf(m2 - mn);
        mx = mn;
    }
    float inv = (deg > 0) ? 1.0f / den : 0.0f;
    float attk = (lane < deg) ? __expf(ek - mx) * inv : 0.0f;

    // aggregation: fp16 rows — one 128B line per row, half2 per lane
    float2 acc = make_float2(0.f, 0.f);
    int cnt = min(deg, 32);
    for (int t = 0; t < cnt; t += 8) {
        int dd[8]; float aa[8]; __half2 hh[8];
#pragma unroll
        for (int u = 0; u < 8; ++u) {
            dd[u] = __shfl_sync(0xffffffffu, dk, t + u);
            aa[u] = __shfl_sync(0xffffffffu, attk, t + u);
        }
#pragma unroll
        for (int u = 0; u < 8; ++u)
            hh[u] = *(const __half2*)(g_Hw1h + (size_t)dd[u] * HID + lane * 2);
#pragma unroll
        for (int u = 0; u < 8; ++u) {
            float2 h = __half22float2(hh[u]);
            acc.x = fmaf(aa[u], h.x, acc.x);
            acc.y = fmaf(aa[u], h.y, acc.y);
        }
    }
    for (int base = beg + 32; base < end; base += 32) {
        int k = base + lane;
        int dk2 = 0; float att2 = 0.f;
        if (k < end) {
            dk2 = g_csr_dst[k];
            float e = sn + g_d[dk2];
            e = e > 0.f ? e : NEG_SLOPE * e;
            att2 = __expf(e - mx) * inv;
        }
        int cnt2 = min(32, end - base);
        for (int t = 0; t < cnt2; t += 8) {
            int dd[8]; float aa[8]; __half2 hh[8];
#pragma unroll
            for (int u = 0; u < 8; ++u) {
                dd[u] = __shfl_sync(0xffffffffu, dk2, t + u);
                aa[u] = __shfl_sync(0xffffffffu, att2, t + u);
            }
#pragma unroll
            for (int u = 0; u < 8; ++u)
                hh[u] = *(const __half2*)(g_Hw1h + (size_t)dd[u] * HID + lane * 2);
#pragma unroll
            for (int u = 0; u < 8; ++u) {
                float2 h = __half22float2(hh[u]);
                acc.x = fmaf(aa[u], h.x, acc.x);
                acc.y = fmaf(aa[u], h.y, acc.y);
            }
        }
    }
    acc.x = acc.x > 0.f ? acc.x : expm1f(acc.x);
    acc.y = acc.y > 0.f ? acc.y : expm1f(acc.y);

    float o2 = 0.f;
#pragma unroll
    for (int k = 0; k < 32; ++k) {
        float hx = __shfl_sync(0xffffffffu, acc.x, k);
        float hy = __shfl_sync(0xffffffffu, acc.y, k);
        o2 = fmaf(hx, W2s[(2 * k) * CLS + lane], o2);
        o2 = fmaf(hy, W2s[(2 * k + 1) * CLS + lane], o2);
    }
    g_Hw2[n * CLS + lane] = o2;

    float sp = o2 * A2s[lane];
    float dp = o2 * A2s[CLS + lane];
#pragma unroll
    for (int o = 16; o > 0; o >>= 1) {
        sp += __shfl_down_sync(0xffffffffu, sp, o);
        dp += __shfl_down_sync(0xffffffffu, dp, o);
    }
    if (lane == 0) { g_s2[n] = sp; g_d2[n] = dp; }
}

// ================= layer-2 softagg + log_softmax (fp32 Hw2) ==================
__global__ void k_softagg32(float* __restrict__ out) {
    int n = blockIdx.x * 8 + (threadIdx.x >> 5);
    int lane = threadIdx.x & 31;
    int beg = seg_beg(n), end = seg_end(n);
    int deg = end - beg;
    float sn = g_s2[n];

    int dk = 0; float ek = -1e30f;
    if (lane < deg) {
        dk = g_csr_dst[beg + lane];
        float e = sn + g_d2[dk];
        ek = e > 0.f ? e : NEG_SLOPE * e;
    }

    float mx = -1e30f, den = 0.f;
    if (deg > 32) {
        for (int k = beg + 32 + lane; k < end; k += 32) {
            int d2 = g_csr_dst[k];
            float e = sn + g_d2[d2];
            e = e > 0.f ? e : NEG_SLOPE * e;
            float mn = fmaxf(mx, e);
            den = den * __expf(mx - mn) + __expf(e - mn);
            mx = mn;
        }
    }
    {
        float mn = fmaxf(mx, ek);
        den = den * __expf(mx - mn) + ((lane < deg) ? __expf(ek - mn) : 0.f);
        mx = mn;
    }
#pragma unroll
    for (int o = 16; o > 0; o >>= 1) {
        float m2 = __shfl_xor_sync(0xffffffffu, mx, o);
        float d2 = __shfl_xor_sync(0xffffffffu, den, o);
        float mn = fmaxf(mx, m2);
        den = den * __expf(mx - mn) + d2 * __expf(m2 - mn);
        mx = mn;
    }
    float inv = (deg > 0) ? 1.0f / den : 0.0f;
    float attk = (lane < deg) ? __expf(ek - mx) * inv : 0.0f;

    float acc = 0.f;
    int cnt = min(deg, 32);
    for (int t = 0; t < cnt; t += 8) {
        int dd[8]; float aa[8]; float hh[8];
#pragma unroll
        for (int u = 0; u < 8; ++u) {
            dd[u] = __shfl_sync(0xffffffffu, dk, t + u);
            aa[u] = __shfl_sync(0xffffffffu, attk, t + u);
        }
#pragma unroll
        for (int u = 0; u < 8; ++u)
            hh[u] = g_Hw2[dd[u] * CLS + lane];
#pragma unroll
        for (int u = 0; u < 8; ++u)
            acc = fmaf(aa[u], hh[u], acc);
    }
    for (int base = beg + 32; base < end; base += 32) {
        int k = base + lane;
        int dk2 = 0; float att2 = 0.f;
        if (k < end) {
            dk2 = g_csr_dst[k];
            float e = sn + g_d2[dk2];
            e = e > 0.f ? e : NEG_SLOPE * e;
            att2 = __expf(e - mx) * inv;
        }
        int cnt2 = min(32, end - base);
        for (int t = 0; t < cnt2; t += 8) {
            int dd[8]; float aa[8]; float hh[8];
#pragma unroll
            for (int u = 0; u < 8; ++u) {
                dd[u] = __shfl_sync(0xffffffffu, dk2, t + u);
                aa[u] = __shfl_sync(0xffffffffu, att2, t + u);
            }
#pragma unroll
            for (int u = 0; u < 8; ++u)
                hh[u] = g_Hw2[dd[u] * CLS + lane];
#pragma unroll
            for (int u = 0; u < 8; ++u)
                acc = fmaf(aa[u], hh[u], acc);
        }
    }
    float m2 = acc;
#pragma unroll
    for (int o = 16; o > 0; o >>= 1) m2 = fmaxf(m2, __shfl_xor_sync(0xffffffffu, m2, o));
    float ex = __expf(acc - m2);
    float sm = ex;
#pragma unroll
    for (int o = 16; o > 0; o >>= 1) sm += __shfl_xor_sync(0xffffffffu, sm, o);
    out[n * CLS + lane] = acc - m2 - __logf(sm);
}

// ================= launch ====================================================
extern "C" void kernel_launch(void* const* d_in, const int* in_sizes, int n_in,
                              void* d_out, int out_size) {
    const float* X  = (const float*)d_in[0];
    const int*   EI = (const int*)d_in[1];
    const float* W1 = (const float*)d_in[2];
    const float* W2 = (const float*)d_in[3];
    const float* A1 = (const float*)d_in[4];
    const float* A2 = (const float*)d_in[5];
    float* out = (float*)d_out;

    static bool s_init = false;
    if (!s_init) {
        cudaFuncSetAttribute(k_gemm1_mma,
                             cudaFuncAttributeMaxDynamicSharedMemorySize, GEMM1_SMEM);
        s_init = true;
    }

    const int T = 256;
    int g_nodes = (N_NODES + T - 1) / T;       // 391
    int g_edges = (N_EDGES + T - 1) / T;       // 6250

    k_init_pack<<<g_nodes, T>>>(W1);
    k_count<<<g_edges, T>>>(EI);
    k_scan1<<<NBLK_SCAN, 256>>>();
    k_scan2<<<1, 512>>>();
    k_fill<<<g_edges, T>>>(EI);

    k_gemm1_mma<<<(N_NODES + BM - 1) / BM, 256, GEMM1_SMEM>>>(X, A1);
    k_softagg64g2<<<N_NODES / 8, 256>>>(W2, A2);
    k_softagg32<<<N_NODES / 8, 256>>>(out);
}